// round 14
// baseline (speedup 1.0000x reference)
#include <cuda_runtime.h>

// EEG_SimpleLSM: 3-layer LIF winner-take-all liquid state machine.
// x: [256, 32, 4000] f32, W1: [64,32], W2: [128,64]. Output: exp(pre_v2@T-1) [256,128].
//
// ROUND 14 = ROUND 13 + phase-split collectives. R13 counters: busiest SMSP
// issues only 41% of cycles while hosting 2 warps -> stages latency-bound
// internally. L0 costs ~73 cyc/step for ~17 instr: each step's
// __reduce_max_sync sits between that step's recurrence and the next's, and
// the compiler does not hoist charge math across the sync intrinsic. Fix in
// source (same trick that made weight prefetch work): per 8-step group,
//   phase 1: 8 steps of charge/reset recurrence only (ch values -> regs),
//   phase 2: 8 independent fkey -> REDUX -> predicated-store sequences,
//            which pipeline at REDUX throughput instead of latency.
// Applied to L0 and L1; L2 (collective-free) unchanged from R13.
//
// Everything else frozen from R13: 3 warps/sample (192 thr, grid 128,
// SMSP0/1 = L0+L2, SMSP2/3 = L1 alone), 80-step double-buffered token
// streams, weight prefetch (MLP=8), packed g_W2F, single-collective argmax
// with predicated same-address store, no "memory" clobber,
// __launch_bounds__(192,1). Identical ops per value in identical step order
// -> rel_err must remain exactly 4.882994e-08.

#define NB    256
#define NCH   32
#define NT    4000
#define CHUNK 80
#define NCHK  (NT / CHUNK)     // 50
#define NBLK8 (NT / 8)         // 500

__device__ __align__(16) float  g_W1T[32 * 64];    // [idx0][2l..2l+1] pairs
__device__ __align__(16) float4 g_W2F[64 * 32];    // [idx1][lane] = (n2l, n2l+1, n64+l, n96+l)

__global__ void prep_kernel(const float* __restrict__ W1, const float* __restrict__ W2) {
    int tid = blockIdx.x * blockDim.x + threadIdx.x;
    int nthr = blockDim.x * gridDim.x;
    for (int i = tid; i < 64 * 32; i += nthr) {
        int r = i >> 5, c = i & 31;
        g_W1T[c * 64 + r] = W1[i];          // W1 is [64][32]
    }
    for (int i = tid; i < 64 * 32; i += nthr) {
        int c = i >> 5, l = i & 31;         // c = idx1 (W2 column), l = lane
        float4 v;
        v.x = W2[(2 * l)     * 64 + c];
        v.y = W2[(2 * l + 1) * 64 + c];
        v.z = W2[(64 + l)    * 64 + c];
        v.w = W2[(96 + l)    * 64 + c];
        g_W2F[i] = v;
    }
}

// Correctly-rounded division by constant c (rc = RN(1/c)), Markstein sequence.
__device__ __forceinline__ float divc(float v, float c, float rc) {
    float q = v * rc;
    float r = __fmaf_rn(-c, q, v);
    return __fmaf_rn(r, rc, q);
}

// Monotone key: strictly order-preserving float -> unsigned mapping.
__device__ __forceinline__ unsigned fkey(float v) {
    unsigned b = __float_as_uint(v);
    return b ^ ((unsigned)((int)b >> 31) | 0x80000000u);
}

// key(1.5f): 0x3FC00000 -> 0xBFC00000 ; key(1.2f): 0x3F99999A -> 0xBF99999A
#define KEY_VTH0 0xBFC00000u
#define KEY_VTH1 0xBF99999Au

__device__ __forceinline__ unsigned smem_u32(const void* p) {
    unsigned r;
    asm("{ .reg .u64 t; cvta.to.shared.u64 t, %1; cvt.u32.u64 %0, t; }"
        : "=r"(r) : "l"(p));
    return r;
}

// Predicated shared store (no BSSY, no "memory" clobber).
__device__ __forceinline__ void sts_if(unsigned cond, unsigned addr, unsigned val) {
    asm volatile(
        "{\n\t"
        ".reg .pred p;\n\t"
        "setp.ne.u32 p, %0, 0;\n\t"
        "@p st.shared.u32 [%1], %2;\n\t"
        "}"
        :: "r"(cond), "r"(addr), "r"(val));
}

__global__ void __launch_bounds__(192, 1)
lsm_kernel(const float* __restrict__ x, float* __restrict__ out) {
    // token streams: [sample][buffer][step-in-chunk]
    __shared__ unsigned s0tok[2][2][CHUNK];
    __shared__ unsigned s1tok[2][2][CHUNK];

    const int tid  = threadIdx.x;
    const int lane = tid & 31;
    const int warp = tid >> 5;
    const int samp = warp & 1;
    const int role = warp >> 1;     // 0 = L0, 1 = L1, 2 = L2
    const int b    = (blockIdx.x << 1) + samp;

    const float RCT = 1.0f / 80000.0f;

    // --- L0 state ---
    float v0 = 0.0f;
    float4 c0, c1;
    int gblk = 0;
    // --- L1 state ---
    float v1a = 0.0f, v1b = 0.0f;
    // --- L2 state ---
    float4 v2 = make_float4(0.f, 0.f, 0.f, 0.f);
    float4 pc = make_float4(0.f, 0.f, 0.f, 0.f);

    const float4* xp  = reinterpret_cast<const float4*>(x + (size_t)b * (NCH * NT) + lane * NT);
    const float2* w1p = reinterpret_cast<const float2*>(g_W1T);
    const float4* w2p = g_W2F;

    if (role == 0) { c0 = __ldg(xp); c1 = __ldg(xp + 1); }

    for (int c = 0; c <= NCHK + 1; ++c) {
        if (role == 0) {
            // ---- L0 chunk c: produce s0 tokens ----
            if (c < NCHK) {
                unsigned tba = smem_u32(&s0tok[samp][c & 1][0]);
                for (int k = 0; k < CHUNK / 8; ++k) {
                    int nb = (gblk + 1 < NBLK8) ? (gblk + 1) * 2 : 0;
                    float4 n0 = __ldg(xp + nb);
                    float4 n1 = __ldg(xp + nb + 1);
                    float xs[8] = {c0.x, c0.y, c0.z, c0.w, c1.x, c1.y, c1.z, c1.w};
                    // phase 1: recurrence only
                    float chs[8];
#pragma unroll
                    for (int j = 0; j < 8; ++j) {
                        float d0  = divc(v0, 3.0f, 1.0f / 3.0f);
                        float ch0 = (v0 + xs[j]) - d0;
                        chs[j] = ch0;
                        v0 = (ch0 >= 1.5f) ? 0.0f : ch0;
                    }
                    // phase 2: independent collectives (pipeline at REDUX rt)
#pragma unroll
                    for (int j = 0; j < 8; ++j) {
                        unsigned k0 = fkey(chs[j]);
                        unsigned m0 = __reduce_max_sync(0xFFFFFFFFu, k0);
                        unsigned tok = (unsigned)lane | ((m0 >= KEY_VTH0) ? 0x80000000u : 0u);
                        sts_if((unsigned)(k0 == m0), tba + (unsigned)((k * 8 + j) * 4), tok);
                    }
                    c0 = n0; c1 = n1; ++gblk;
                }
            }
        } else if (role == 1) {
            // ---- L1 chunk c-1: consume s0 tokens, produce s1 tokens ----
            if (c >= 1 && c <= NCHK) {
                const unsigned* sb = &s0tok[samp][(c - 1) & 1][0];
                unsigned tba = smem_u32(&s1tok[samp][(c - 1) & 1][0]);
                for (int k = 0; k < CHUNK / 8; ++k) {
                    unsigned toks[8];
                    float2 wv[8];
#pragma unroll
                    for (int j = 0; j < 8; ++j) toks[j] = sb[k * 8 + j];
#pragma unroll
                    for (int j = 0; j < 8; ++j)    // weight prefetch (MLP=8)
                        wv[j] = __ldg(w1p + ((toks[j] & 0x7FFFFFFFu) << 5) + lane);
                    // phase 1: recurrence only
                    float chas[8], chbs[8];
#pragma unroll
                    for (int j = 0; j < 8; ++j) {
                        float s0 = (toks[j] & 0x80000000u) ? 1.0f : 0.0f;
                        float d1a = divc(v1a, 80000.0f, RCT);
                        float d1b = divc(v1b, 80000.0f, RCT);
                        float cha = __fmaf_rn(wv[j].x, s0, v1a) - d1a;  // exact: s0 in {0,1}
                        float chb = __fmaf_rn(wv[j].y, s0, v1b) - d1b;
                        chas[j] = cha; chbs[j] = chb;
                        v1a = (cha >= 1.2f) ? 0.0f : cha;
                        v1b = (chb >= 1.2f) ? 0.0f : chb;
                    }
                    // phase 2: independent collectives
#pragma unroll
                    for (int j = 0; j < 8; ++j) {
                        unsigned ka = fkey(chas[j]);
                        unsigned kb = fkey(chbs[j]);
                        bool bw = kb > ka;
                        unsigned lk = bw ? kb : ka;
                        unsigned li = 2u * (unsigned)lane + (bw ? 1u : 0u);
                        unsigned m1 = __reduce_max_sync(0xFFFFFFFFu, lk);
                        unsigned tok1 = li | ((m1 >= KEY_VTH1) ? 0x80000000u : 0u);
                        sts_if((unsigned)(lk == m1), tba + (unsigned)((k * 8 + j) * 4), tok1);
                    }
                }
            }
        } else {
            // ---- L2 chunk c-2: consume s1 tokens ----
            if (c >= 2) {
                const unsigned* sb = &s1tok[samp][c & 1][0];
                for (int k = 0; k < CHUNK / 8; ++k) {
                    unsigned toks[8];
                    float4 wv[8];
#pragma unroll
                    for (int j = 0; j < 8; ++j) toks[j] = sb[k * 8 + j];
#pragma unroll
                    for (int j = 0; j < 8; ++j)    // weight prefetch (MLP=8)
                        wv[j] = __ldg(w2p + ((toks[j] & 0x7FFFFFFFu) << 5) + lane);
#pragma unroll
                    for (int j = 0; j < 8; ++j) {
                        float s1 = (toks[j] & 0x80000000u) ? 1.0f : 0.0f;
                        float dx = divc(v2.x, 80000.0f, RCT);
                        float dy = divc(v2.y, 80000.0f, RCT);
                        float dz = divc(v2.z, 80000.0f, RCT);
                        float dw = divc(v2.w, 80000.0f, RCT);
                        pc.x = __fmaf_rn(wv[j].x, s1, v2.x) - dx;
                        pc.y = __fmaf_rn(wv[j].y, s1, v2.y) - dy;
                        pc.z = __fmaf_rn(wv[j].z, s1, v2.z) - dz;
                        pc.w = __fmaf_rn(wv[j].w, s1, v2.w) - dw;
                        v2.x = (pc.x >= 1.2f) ? 0.0f : pc.x;
                        v2.y = (pc.y >= 1.2f) ? 0.0f : pc.y;
                        v2.z = (pc.z >= 1.2f) ? 0.0f : pc.z;
                        v2.w = (pc.w >= 1.2f) ? 0.0f : pc.w;
                    }
                }
            }
        }
        __syncthreads();
    }

    // Output: liquid state = exp(pre-reset v2 at step NT-1). L2 warp owns all.
    if (role == 2) {
        float* ob = out + (size_t)b * 128;
        float2 o2; o2.x = expf(pc.x); o2.y = expf(pc.y);
        reinterpret_cast<float2*>(ob)[lane] = o2;        // neurons 2l, 2l+1
        ob[64 + lane] = expf(pc.z);                      // neuron 64+l
        ob[96 + lane] = expf(pc.w);                      // neuron 96+l
    }
}

extern "C" void kernel_launch(void* const* d_in, const int* in_sizes, int n_in,
                              void* d_out, int out_size) {
    const float* x  = (const float*)d_in[0];
    const float* W1 = (const float*)d_in[1];
    const float* W2 = (const float*)d_in[2];
    float* out = (float*)d_out;

    prep_kernel<<<1, 256>>>(W1, W2);
    lsm_kernel<<<NB / 2, 192>>>(x, out);
}

// round 15
// speedup vs baseline: 1.0116x; 1.0116x over previous
#include <cuda_runtime.h>

// EEG_SimpleLSM: 3-layer LIF winner-take-all liquid state machine.
// x: [256, 32, 4000] f32, W1: [64,32], W2: [128,64]. Output: exp(pre_v2@T-1) [256,128].
//
// ROUND 15 = R13 loop bodies (R14's phase split regressed; reverted) + two
// fixes for R13's measured ~2x stall overhead on the L0+L2 SMSP:
//  1. Deeper x prefetch (distance 2 blocks): R13's 1-block distance (~160 cyc
//     of L0 work) < ~380+ cyc effective DRAM latency -> ~25 cyc/step exposed.
//     HBM rate (512 GB/s needed, 532 measured) is fine; depth wasn't.
//  2. 4 warps/sample (256 thr/CTA, grid 128): L2 split into L2a (neurons
//     0..95, 3/lane) + L2b (96..127, 1/lane). SMSP loads: L0+L2a ~43,
//     L1+L2b ~44 instr/step (was 50/35 unbalanced), and stalls of
//     co-resident warps interleave in HW.
// Retained: 80-step double-buffered token streams, same-step token
// consumption (L0 c=0..49, L1 c=1..50, L2 c=2..51), token+weight prefetch in
// groups of 8 (MLP=8), packed g_W2F / g_W2A, single-collective argmax with
// predicated same-address store, no "memory" clobber, __launch_bounds__(256,1).
// All per-value arithmetic bit-identical to R3..R14 -> rel_err must remain
// exactly 4.882994e-08.

#define NB    256
#define NCH   32
#define NT    4000
#define CHUNK 80
#define NCHK  (NT / CHUNK)     // 50
#define NBLK8 (NT / 8)         // 500

__device__ __align__(16) float  g_W1T[32 * 64];    // [idx0][2l..2l+1] pairs
__device__ __align__(16) float4 g_W2F[64 * 32];    // [idx1][lane] = (n2l, n2l+1, n64+l, n96+l)
__device__ __align__(16) float  g_W2A[64 * 32];    // [idx1][lane] = n96+l

__global__ void prep_kernel(const float* __restrict__ W1, const float* __restrict__ W2) {
    int tid = blockIdx.x * blockDim.x + threadIdx.x;
    int nthr = blockDim.x * gridDim.x;
    for (int i = tid; i < 64 * 32; i += nthr) {
        int r = i >> 5, c = i & 31;
        g_W1T[c * 64 + r] = W1[i];          // W1 is [64][32]
    }
    for (int i = tid; i < 64 * 32; i += nthr) {
        int c = i >> 5, l = i & 31;         // c = idx1 (W2 column), l = lane
        float4 v;
        v.x = W2[(2 * l)     * 64 + c];
        v.y = W2[(2 * l + 1) * 64 + c];
        v.z = W2[(64 + l)    * 64 + c];
        v.w = W2[(96 + l)    * 64 + c];
        g_W2F[i] = v;
        g_W2A[i] = v.w;
    }
}

// Correctly-rounded division by constant c (rc = RN(1/c)), Markstein sequence.
__device__ __forceinline__ float divc(float v, float c, float rc) {
    float q = v * rc;
    float r = __fmaf_rn(-c, q, v);
    return __fmaf_rn(r, rc, q);
}

// Monotone key: strictly order-preserving float -> unsigned mapping.
__device__ __forceinline__ unsigned fkey(float v) {
    unsigned b = __float_as_uint(v);
    return b ^ ((unsigned)((int)b >> 31) | 0x80000000u);
}

// key(1.5f): 0x3FC00000 -> 0xBFC00000 ; key(1.2f): 0x3F99999A -> 0xBF99999A
#define KEY_VTH0 0xBFC00000u
#define KEY_VTH1 0xBF99999Au

__device__ __forceinline__ unsigned smem_u32(const void* p) {
    unsigned r;
    asm("{ .reg .u64 t; cvta.to.shared.u64 t, %1; cvt.u32.u64 %0, t; }"
        : "=r"(r) : "l"(p));
    return r;
}

// Predicated shared store (no BSSY, no "memory" clobber).
__device__ __forceinline__ void sts_if(unsigned cond, unsigned addr, unsigned val) {
    asm volatile(
        "{\n\t"
        ".reg .pred p;\n\t"
        "setp.ne.u32 p, %0, 0;\n\t"
        "@p st.shared.u32 [%1], %2;\n\t"
        "}"
        :: "r"(cond), "r"(addr), "r"(val));
}

__global__ void __launch_bounds__(256, 1)
lsm_kernel(const float* __restrict__ x, float* __restrict__ out) {
    // token streams: [sample][buffer][step-in-chunk]
    __shared__ unsigned s0tok[2][2][CHUNK];
    __shared__ unsigned s1tok[2][2][CHUNK];

    const int tid  = threadIdx.x;
    const int lane = tid & 31;
    const int warp = tid >> 5;
    const int samp = warp & 1;
    const int role = warp >> 1;     // 0 = L0, 1 = L1, 2 = L2a (n 0..95), 3 = L2b (n 96..127)
    const int b    = (blockIdx.x << 1) + samp;
    // SMSP = warp & 3: SMSP0/1 = {L0, L2a}, SMSP2/3 = {L1, L2b} per sample.

    const float RCT = 1.0f / 80000.0f;

    // --- L0 state ---
    float v0 = 0.0f;
    float4 c0, c1, n0, n1;
    int gblk = 0;
    // --- L1 state ---
    float v1a = 0.0f, v1b = 0.0f;
    // --- L2a state (neurons 2l, 2l+1, 64+l) ---
    float v2x = 0.0f, v2y = 0.0f, v2z = 0.0f;
    float pcx = 0.0f, pcy = 0.0f, pcz = 0.0f;
    // --- L2b state (neuron 96+l) ---
    float v2w = 0.0f, pcw = 0.0f;

    const float4* xp  = reinterpret_cast<const float4*>(x + (size_t)b * (NCH * NT) + lane * NT);
    const float2* w1p = reinterpret_cast<const float2*>(g_W1T);
    const float4* w2p = g_W2F;
    const float*  w2b = g_W2A;

    if (role == 0) {
        c0 = __ldg(xp);     c1 = __ldg(xp + 1);     // block 0
        n0 = __ldg(xp + 2); n1 = __ldg(xp + 3);     // block 1
    }

    for (int c = 0; c <= NCHK + 1; ++c) {
        if (role == 0) {
            // ---- L0 chunk c: produce s0 tokens (prefetch distance 2) ----
            if (c < NCHK) {
                unsigned tba = smem_u32(&s0tok[samp][c & 1][0]);
                for (int k = 0; k < CHUNK / 8; ++k) {
                    int nb2 = (gblk + 2 < NBLK8) ? (gblk + 2) * 2 : 0;
                    float4 m0 = __ldg(xp + nb2);
                    float4 m1 = __ldg(xp + nb2 + 1);
                    float xs[8] = {c0.x, c0.y, c0.z, c0.w, c1.x, c1.y, c1.z, c1.w};
#pragma unroll
                    for (int j = 0; j < 8; ++j) {
                        float d0  = divc(v0, 3.0f, 1.0f / 3.0f);
                        float ch0 = (v0 + xs[j]) - d0;
                        unsigned k0 = fkey(ch0);
                        unsigned m0r = __reduce_max_sync(0xFFFFFFFFu, k0);
                        unsigned tok = (unsigned)lane | ((m0r >= KEY_VTH0) ? 0x80000000u : 0u);
                        sts_if((unsigned)(k0 == m0r), tba + (unsigned)((k * 8 + j) * 4), tok);
                        v0 = (ch0 >= 1.5f) ? 0.0f : ch0;
                    }
                    c0 = n0; c1 = n1;   // shift queue
                    n0 = m0; n1 = m1;
                    ++gblk;
                }
            }
        } else if (role == 1) {
            // ---- L1 chunk c-1: consume s0 tokens, produce s1 tokens ----
            if (c >= 1 && c <= NCHK) {
                const unsigned* sb = &s0tok[samp][(c - 1) & 1][0];
                unsigned tba = smem_u32(&s1tok[samp][(c - 1) & 1][0]);
                for (int k = 0; k < CHUNK / 8; ++k) {
                    unsigned toks[8];
                    float2 wv[8];
#pragma unroll
                    for (int j = 0; j < 8; ++j) toks[j] = sb[k * 8 + j];
#pragma unroll
                    for (int j = 0; j < 8; ++j)    // weight prefetch (MLP=8)
                        wv[j] = __ldg(w1p + ((toks[j] & 0x7FFFFFFFu) << 5) + lane);
#pragma unroll
                    for (int j = 0; j < 8; ++j) {
                        float s0 = (toks[j] & 0x80000000u) ? 1.0f : 0.0f;
                        float d1a = divc(v1a, 80000.0f, RCT);
                        float d1b = divc(v1b, 80000.0f, RCT);
                        float cha = __fmaf_rn(wv[j].x, s0, v1a) - d1a;  // exact: s0 in {0,1}
                        float chb = __fmaf_rn(wv[j].y, s0, v1b) - d1b;
                        unsigned ka = fkey(cha);
                        unsigned kb = fkey(chb);
                        bool bw = kb > ka;
                        unsigned lk = bw ? kb : ka;
                        unsigned li = 2u * (unsigned)lane + (bw ? 1u : 0u);
                        unsigned m1 = __reduce_max_sync(0xFFFFFFFFu, lk);
                        unsigned tok1 = li | ((m1 >= KEY_VTH1) ? 0x80000000u : 0u);
                        sts_if((unsigned)(lk == m1), tba + (unsigned)((k * 8 + j) * 4), tok1);
                        v1a = (cha >= 1.2f) ? 0.0f : cha;
                        v1b = (chb >= 1.2f) ? 0.0f : chb;
                    }
                }
            }
        } else if (role == 2) {
            // ---- L2a chunk c-2: neurons 2l, 2l+1, 64+l ----
            if (c >= 2) {
                const unsigned* sb = &s1tok[samp][c & 1][0];
                for (int k = 0; k < CHUNK / 8; ++k) {
                    unsigned toks[8];
                    float4 wv[8];
#pragma unroll
                    for (int j = 0; j < 8; ++j) toks[j] = sb[k * 8 + j];
#pragma unroll
                    for (int j = 0; j < 8; ++j)    // weight prefetch (MLP=8)
                        wv[j] = __ldg(w2p + ((toks[j] & 0x7FFFFFFFu) << 5) + lane);
#pragma unroll
                    for (int j = 0; j < 8; ++j) {
                        float s1 = (toks[j] & 0x80000000u) ? 1.0f : 0.0f;
                        float dx = divc(v2x, 80000.0f, RCT);
                        float dy = divc(v2y, 80000.0f, RCT);
                        float dz = divc(v2z, 80000.0f, RCT);
                        pcx = __fmaf_rn(wv[j].x, s1, v2x) - dx;
                        pcy = __fmaf_rn(wv[j].y, s1, v2y) - dy;
                        pcz = __fmaf_rn(wv[j].z, s1, v2z) - dz;
                        v2x = (pcx >= 1.2f) ? 0.0f : pcx;
                        v2y = (pcy >= 1.2f) ? 0.0f : pcy;
                        v2z = (pcz >= 1.2f) ? 0.0f : pcz;
                    }
                }
            }
        } else {
            // ---- L2b chunk c-2: neuron 96+l ----
            if (c >= 2) {
                const unsigned* sb = &s1tok[samp][c & 1][0];
                for (int k = 0; k < CHUNK / 8; ++k) {
                    unsigned toks[8];
                    float wv[8];
#pragma unroll
                    for (int j = 0; j < 8; ++j) toks[j] = sb[k * 8 + j];
#pragma unroll
                    for (int j = 0; j < 8; ++j)    // weight prefetch (MLP=8)
                        wv[j] = __ldg(w2b + ((toks[j] & 0x7FFFFFFFu) << 5) + lane);
#pragma unroll
                    for (int j = 0; j < 8; ++j) {
                        float s1 = (toks[j] & 0x80000000u) ? 1.0f : 0.0f;
                        float dw = divc(v2w, 80000.0f, RCT);
                        pcw = __fmaf_rn(wv[j], s1, v2w) - dw;
                        v2w = (pcw >= 1.2f) ? 0.0f : pcw;
                    }
                }
            }
        }
        __syncthreads();
    }

    // Output: liquid state = exp(pre-reset v2 at step NT-1). Disjoint ranges.
    float* ob = out + (size_t)b * 128;
    if (role == 2) {
        float2 o2; o2.x = expf(pcx); o2.y = expf(pcy);
        reinterpret_cast<float2*>(ob)[lane] = o2;        // neurons 2l, 2l+1
        ob[64 + lane] = expf(pcz);                       // neuron 64+l
    } else if (role == 3) {
        ob[96 + lane] = expf(pcw);                       // neuron 96+l
    }
}

extern "C" void kernel_launch(void* const* d_in, const int* in_sizes, int n_in,
                              void* d_out, int out_size) {
    const float* x  = (const float*)d_in[0];
    const float* W1 = (const float*)d_in[1];
    const float* W2 = (const float*)d_in[2];
    float* out = (float*)d_out;

    prep_kernel<<<1, 256>>>(W1, W2);
    lsm_kernel<<<NB / 2, 256>>>(x, out);
}

// round 17
// speedup vs baseline: 1.4647x; 1.4479x over previous
#include <cuda_runtime.h>

// EEG_SimpleLSM: 3-layer LIF winner-take-all liquid state machine.
// x: [256, 32, 4000] f32, W1: [64,32], W2: [128,64]. Output: exp(pre_v2@T-1) [256,128].
//
// ROUND 17 = ROUND 16 with the macro/field-name collision fixed (CMP4's
// parameter `w` was substituted into `.w` accessors; now an inline function).
//
// Theory under test (R16): R13/14/15 plateau at ~122-126 cyc/step across
// different warp configs = shared per-SM collective unit at its floor:
// 4 REDUX/step/SM x ~32 cyc = 128. Fix: remove ALL warp collectives.
// Each 32-step group:
//   R phase (lanewise): recurrence + store charge row to padded smem tile
//     (L0: [32][36], L1: [32][68] -> conflict-free row reads).
//   X phase (lane = step): pairwise FSETP/SEL tree over the lane's row;
//     left-biased '>' keeps lowest index on block-ordered ties (ties at max
//     validated inconsequential in R12; rel_err canary). Token stored by its
//     own lane -- plain STS, no predication, no collectives.
// CHUNK=160 (5 groups of 32), NCHK=25, 27 barriers. Rest frozen from R15:
// 4 roles x 2 samples (256 thr, grid 128), token+weight prefetch (MLP=8),
// packed g_W2F/g_W2A, distance-2 x prefetch, __launch_bounds__(256,1).
// Charge/reset arithmetic bit-identical -> rel_err must stay 4.882994e-08.

#define NB    256
#define NCH   32
#define NT    4000
#define CHUNK 160
#define NCHK  (NT / CHUNK)     // 25
#define NBLK8 (NT / 8)         // 500

__device__ __align__(16) float  g_W1T[32 * 64];    // [idx0][2l..2l+1] pairs
__device__ __align__(16) float4 g_W2F[64 * 32];    // [idx1][lane] = (n2l, n2l+1, n64+l, n96+l)
__device__ __align__(16) float  g_W2A[64 * 32];    // [idx1][lane] = n96+l

__global__ void prep_kernel(const float* __restrict__ W1, const float* __restrict__ W2) {
    int tid = blockIdx.x * blockDim.x + threadIdx.x;
    int nthr = blockDim.x * gridDim.x;
    for (int i = tid; i < 64 * 32; i += nthr) {
        int r = i >> 5, c = i & 31;
        g_W1T[c * 64 + r] = W1[i];          // W1 is [64][32]
    }
    for (int i = tid; i < 64 * 32; i += nthr) {
        int c = i >> 5, l = i & 31;         // c = idx1 (W2 column), l = lane
        float4 v;
        v.x = W2[(2 * l)     * 64 + c];
        v.y = W2[(2 * l + 1) * 64 + c];
        v.z = W2[(64 + l)    * 64 + c];
        v.w = W2[(96 + l)    * 64 + c];
        g_W2F[i] = v;
        g_W2A[i] = v.w;
    }
}

// Correctly-rounded division by constant c (rc = RN(1/c)), Markstein sequence.
__device__ __forceinline__ float divc(float v, float c, float rc) {
    float q = v * rc;
    float r = __fmaf_rn(-c, q, v);
    return __fmaf_rn(r, rc, q);
}

// Pairwise (value,index) combine: take rhs only if strictly greater.
// Left-biased -> lowest block index survives ties.
__device__ __forceinline__ void cmp4(float4& va, int4& ia, const float4& vb, const int4& ib) {
    bool t;
    t = vb.x > va.x; va.x = t ? vb.x : va.x; ia.x = t ? ib.x : ia.x;
    t = vb.y > va.y; va.y = t ? vb.y : va.y; ia.y = t ? ib.y : ia.y;
    t = vb.z > va.z; va.z = t ? vb.z : va.z; ia.z = t ? ib.z : ia.z;
    t = vb.w > va.w; va.w = t ? vb.w : va.w; ia.w = t ? ib.w : ia.w;
}

// Horizontal finish over a float4/int4, then pack token (idx | spike<<31).
// Order keeps the lowest index on ties: x vs z, y vs w, then x-side vs y-side.
__device__ __forceinline__ unsigned argmax_tok(float4 v, int4 id, float vth) {
    bool t;
    float bx = v.x; int ix = id.x;
    t = v.z > bx; bx = t ? v.z : bx; ix = t ? id.z : ix;
    float by = v.y; int iy = id.y;
    t = v.w > by; by = t ? v.w : by; iy = t ? id.w : iy;
    t = by > bx; bx = t ? by : bx; ix = t ? iy : ix;
    return (unsigned)ix | ((bx >= vth) ? 0x80000000u : 0u);
}

__global__ void __launch_bounds__(256, 1)
lsm_kernel(const float* __restrict__ x, float* __restrict__ out) {
    // token streams: [sample][buffer][step-in-chunk]
    __shared__ unsigned s0tok[2][2][CHUNK];
    __shared__ unsigned s1tok[2][2][CHUNK];
    // transpose tiles: [sample][step-in-group][neuron], padded rows
    __shared__ float tr0[2][32][36];
    __shared__ float tr1[2][32][68];

    const int tid  = threadIdx.x;
    const int lane = tid & 31;
    const int warp = tid >> 5;
    const int samp = warp & 1;
    const int role = warp >> 1;     // 0 = L0, 1 = L1, 2 = L2a (n 0..95), 3 = L2b (n 96..127)
    const int b    = (blockIdx.x << 1) + samp;

    const float RCT = 1.0f / 80000.0f;

    // --- L0 state ---
    float v0 = 0.0f;
    float4 c0, c1, n0, n1;
    int gblk = 0;
    // --- L1 state ---
    float v1a = 0.0f, v1b = 0.0f;
    // --- L2a state (neurons 2l, 2l+1, 64+l) ---
    float v2x = 0.0f, v2y = 0.0f, v2z = 0.0f;
    float pcx = 0.0f, pcy = 0.0f, pcz = 0.0f;
    // --- L2b state (neuron 96+l) ---
    float v2w = 0.0f, pcw = 0.0f;

    const float4* xp  = reinterpret_cast<const float4*>(x + (size_t)b * (NCH * NT) + lane * NT);
    const float2* w1p = reinterpret_cast<const float2*>(g_W1T);
    const float4* w2p = g_W2F;
    const float*  w2b = g_W2A;

    if (role == 0) {
        c0 = __ldg(xp);     c1 = __ldg(xp + 1);
        n0 = __ldg(xp + 2); n1 = __ldg(xp + 3);
    }

    for (int c = 0; c <= NCHK + 1; ++c) {
        if (role == 0) {
            // ---- L0 chunk c: produce s0 tokens ----
            if (c < NCHK) {
                unsigned* tb = &s0tok[samp][c & 1][0];
                float* tr = &tr0[samp][0][0];
                for (int g = 0; g < CHUNK / 32; ++g) {
                    // R phase: 32 steps of recurrence, charges -> tile
                    for (int k2 = 0; k2 < 4; ++k2) {
                        int nb2 = (gblk + 2 < NBLK8) ? (gblk + 2) * 2 : 0;
                        float4 m0 = __ldg(xp + nb2);
                        float4 m1 = __ldg(xp + nb2 + 1);
                        float xs[8] = {c0.x, c0.y, c0.z, c0.w, c1.x, c1.y, c1.z, c1.w};
#pragma unroll
                        for (int j = 0; j < 8; ++j) {
                            float d0 = divc(v0, 3.0f, 1.0f / 3.0f);
                            float ch = (v0 + xs[j]) - d0;
                            tr[(k2 * 8 + j) * 36 + lane] = ch;
                            v0 = (ch >= 1.5f) ? 0.0f : ch;
                        }
                        c0 = n0; c1 = n1; n0 = m0; n1 = m1; ++gblk;
                    }
                    __syncwarp();
                    // X phase: lane = step; serial tree over 32 channels
                    const float* trr = tr + lane * 36;
                    float4 v[4]; int4 id[4];
#pragma unroll
                    for (int i = 0; i < 4; ++i) {
                        float4 qa = *reinterpret_cast<const float4*>(trr + i * 4);
                        float4 qb = *reinterpret_cast<const float4*>(trr + (i + 4) * 4);
                        v[i] = qa;
                        id[i] = make_int4(4 * i, 4 * i + 1, 4 * i + 2, 4 * i + 3);
                        int4 jd = make_int4(16 + 4 * i, 17 + 4 * i, 18 + 4 * i, 19 + 4 * i);
                        cmp4(v[i], id[i], qb, jd);
                    }
                    cmp4(v[0], id[0], v[2], id[2]);
                    cmp4(v[1], id[1], v[3], id[3]);
                    cmp4(v[0], id[0], v[1], id[1]);
                    tb[g * 32 + lane] = argmax_tok(v[0], id[0], 1.5f);
                    __syncwarp();
                }
            }
        } else if (role == 1) {
            // ---- L1 chunk c-1: consume s0 tokens, produce s1 tokens ----
            if (c >= 1 && c <= NCHK) {
                const unsigned* sb = &s0tok[samp][(c - 1) & 1][0];
                unsigned* tb = &s1tok[samp][(c - 1) & 1][0];
                float* tr = &tr1[samp][0][0];
                for (int g = 0; g < CHUNK / 32; ++g) {
                    // R phase: 32 steps, charges (2 neurons/lane) -> tile
                    for (int k2 = 0; k2 < 4; ++k2) {
                        unsigned toks[8];
                        float2 wv[8];
#pragma unroll
                        for (int j = 0; j < 8; ++j) toks[j] = sb[g * 32 + k2 * 8 + j];
#pragma unroll
                        for (int j = 0; j < 8; ++j)    // weight prefetch (MLP=8)
                            wv[j] = __ldg(w1p + ((toks[j] & 0x7FFFFFFFu) << 5) + lane);
#pragma unroll
                        for (int j = 0; j < 8; ++j) {
                            float s0 = (toks[j] & 0x80000000u) ? 1.0f : 0.0f;
                            float d1a = divc(v1a, 80000.0f, RCT);
                            float d1b = divc(v1b, 80000.0f, RCT);
                            float cha = __fmaf_rn(wv[j].x, s0, v1a) - d1a;  // exact: s0 in {0,1}
                            float chb = __fmaf_rn(wv[j].y, s0, v1b) - d1b;
                            *reinterpret_cast<float2*>(tr + (k2 * 8 + j) * 68 + 2 * lane)
                                = make_float2(cha, chb);
                            v1a = (cha >= 1.2f) ? 0.0f : cha;
                            v1b = (chb >= 1.2f) ? 0.0f : chb;
                        }
                    }
                    __syncwarp();
                    // X phase: lane = step; serial tree over 64 neurons
                    const float* trr = tr + lane * 68;
                    float4 v[8]; int4 id[8];
#pragma unroll
                    for (int i = 0; i < 8; ++i) {
                        float4 qa = *reinterpret_cast<const float4*>(trr + i * 4);
                        float4 qb = *reinterpret_cast<const float4*>(trr + (i + 8) * 4);
                        v[i] = qa;
                        id[i] = make_int4(4 * i, 4 * i + 1, 4 * i + 2, 4 * i + 3);
                        int4 jd = make_int4(32 + 4 * i, 33 + 4 * i, 34 + 4 * i, 35 + 4 * i);
                        cmp4(v[i], id[i], qb, jd);
                    }
#pragma unroll
                    for (int i = 0; i < 4; ++i) cmp4(v[i], id[i], v[i + 4], id[i + 4]);
                    cmp4(v[0], id[0], v[2], id[2]);
                    cmp4(v[1], id[1], v[3], id[3]);
                    cmp4(v[0], id[0], v[1], id[1]);
                    tb[g * 32 + lane] = argmax_tok(v[0], id[0], 1.2f);
                    __syncwarp();
                }
            }
        } else if (role == 2) {
            // ---- L2a chunk c-2: neurons 2l, 2l+1, 64+l ----
            if (c >= 2) {
                const unsigned* sb = &s1tok[samp][c & 1][0];
                for (int k = 0; k < CHUNK / 8; ++k) {
                    unsigned toks[8];
                    float4 wv[8];
#pragma unroll
                    for (int j = 0; j < 8; ++j) toks[j] = sb[k * 8 + j];
#pragma unroll
                    for (int j = 0; j < 8; ++j)    // weight prefetch (MLP=8)
                        wv[j] = __ldg(w2p + ((toks[j] & 0x7FFFFFFFu) << 5) + lane);
#pragma unroll
                    for (int j = 0; j < 8; ++j) {
                        float s1 = (toks[j] & 0x80000000u) ? 1.0f : 0.0f;
                        float dx = divc(v2x, 80000.0f, RCT);
                        float dy = divc(v2y, 80000.0f, RCT);
                        float dz = divc(v2z, 80000.0f, RCT);
                        pcx = __fmaf_rn(wv[j].x, s1, v2x) - dx;
                        pcy = __fmaf_rn(wv[j].y, s1, v2y) - dy;
                        pcz = __fmaf_rn(wv[j].z, s1, v2z) - dz;
                        v2x = (pcx >= 1.2f) ? 0.0f : pcx;
                        v2y = (pcy >= 1.2f) ? 0.0f : pcy;
                        v2z = (pcz >= 1.2f) ? 0.0f : pcz;
                    }
                }
            }
        } else {
            // ---- L2b chunk c-2: neuron 96+l ----
            if (c >= 2) {
                const unsigned* sb = &s1tok[samp][c & 1][0];
                for (int k = 0; k < CHUNK / 8; ++k) {
                    unsigned toks[8];
                    float wv[8];
#pragma unroll
                    for (int j = 0; j < 8; ++j) toks[j] = sb[k * 8 + j];
#pragma unroll
                    for (int j = 0; j < 8; ++j)    // weight prefetch (MLP=8)
                        wv[j] = __ldg(w2b + ((toks[j] & 0x7FFFFFFFu) << 5) + lane);
#pragma unroll
                    for (int j = 0; j < 8; ++j) {
                        float s1 = (toks[j] & 0x80000000u) ? 1.0f : 0.0f;
                        float dw = divc(v2w, 80000.0f, RCT);
                        pcw = __fmaf_rn(wv[j], s1, v2w) - dw;
                        v2w = (pcw >= 1.2f) ? 0.0f : pcw;
                    }
                }
            }
        }
        __syncthreads();
    }

    // Output: liquid state = exp(pre-reset v2 at step NT-1). Disjoint ranges.
    float* ob = out + (size_t)b * 128;
    if (role == 2) {
        float2 o2; o2.x = expf(pcx); o2.y = expf(pcy);
        reinterpret_cast<float2*>(ob)[lane] = o2;        // neurons 2l, 2l+1
        ob[64 + lane] = expf(pcz);                       // neuron 64+l
    } else if (role == 3) {
        ob[96 + lane] = expf(pcw);                       // neuron 96+l
    }
}

extern "C" void kernel_launch(void* const* d_in, const int* in_sizes, int n_in,
                              void* d_out, int out_size) {
    const float* x  = (const float*)d_in[0];
    const float* W1 = (const float*)d_in[1];
    const float* W2 = (const float*)d_in[2];
    float* out = (float*)d_out;

    prep_kernel<<<1, 256>>>(W1, W2);
    lsm_kernel<<<NB / 2, 256>>>(x, out);
}